// round 8
// baseline (speedup 1.0000x reference)
#include <cuda_runtime.h>
#include <cstdint>

#define NROWS 8192
#define DIM   128
#define BM    128
#define BN    128
#define NTILES (NROWS / BN)                  // 64
#define NUNITS (NTILES * (NTILES + 1) / 2)   // 2080 triangle tile-pairs
#define GRID_MAIN 148
#define RSTRIDE   132                        // floats/row of B smem tile (conflict-free)
#define TILE_F (BM * RSTRIDE)                // 16896 floats per B tile
#define MARGIN_F 0.3f

typedef unsigned long long u64;

// Scratch (device globals; no allocations allowed)
__device__ unsigned int g_ap2[NROWS];   // max same-label d^2 (float bits)
__device__ unsigned int g_an2[NROWS];   // min diff-label d^2 (float bits)
__device__ float        g_sq[NROWS];    // ||x_i||^2
__device__ int          g_lab[NROWS];   // normalized labels (int32)
__device__ unsigned int g_done;         // last-CTA election (reset each launch)

// ---------------------------------------------------------------------------
// Helpers
// ---------------------------------------------------------------------------
__device__ __forceinline__ unsigned smem_u32(const void* p) {
    unsigned r;
    asm("{ .reg .u64 t; cvta.to.shared.u64 t, %1; cvt.u32.u64 %0, t; }"
        : "=r"(r) : "l"(p));
    return r;
}
__device__ __forceinline__ void cp16(unsigned dst, const void* src) {
    asm volatile("cp.async.cg.shared.global [%0], [%1], 16;" :: "r"(dst), "l"(src));
}
__device__ __forceinline__ void cp4(unsigned dst, const void* src) {
    asm volatile("cp.async.ca.shared.global [%0], [%1], 4;" :: "r"(dst), "l"(src));
}
__device__ __forceinline__ void cp_commit() { asm volatile("cp.async.commit_group;"); }
__device__ __forceinline__ void cp_wait0()  { asm volatile("cp.async.wait_group 0;" ::: "memory"); }
__device__ __forceinline__ void cp_wait1()  { asm volatile("cp.async.wait_group 1;" ::: "memory"); }

// ---------------------------------------------------------------------------
// Fused prep: init mining buffers + row norms + label normalization.
// ---------------------------------------------------------------------------
__global__ void prep_kernel(const float* __restrict__ x, const int* __restrict__ t32) {
    int gid = blockIdx.x * 256 + threadIdx.x;
    if (gid < NROWS) { g_ap2[gid] = 0u; g_an2[gid] = 0x7f800000u; }

    int gwarp = gid >> 5;          // exactly 8192 warps
    int lane  = gid & 31;
    float4 v = reinterpret_cast<const float4*>(x + (size_t)gwarp * DIM)[lane];
    float s = v.x * v.x + v.y * v.y + v.z * v.z + v.w * v.w;
#pragma unroll
    for (int o = 16; o; o >>= 1) s += __shfl_xor_sync(0xffffffffu, s, o);
    if (lane == 0) g_sq[gwarp] = s;

    if (blockIdx.x == 0) {
        // targets may be int64 (odd int32 words all zero) or int32
        __shared__ int s_all64;
        if (threadIdx.x == 0) s_all64 = 1;
        __syncthreads();
        int local = 1;
        for (int i = threadIdx.x; i < 4096; i += 256)
            if (t32[2 * i + 1] != 0) local = 0;
        if (!local) atomicAnd(&s_all64, 0);
        __syncthreads();
        const bool is64 = (s_all64 != 0);
        for (int i = threadIdx.x; i < NROWS; i += 256)
            g_lab[i] = is64 ? t32[2 * i] : t32[i];
    }
}

// ---------------------------------------------------------------------------
// B tile loader: global row-major [rows][128] -> smem rows stride 132 floats.
// cp.async.cg (L2-only) keeps L1 free for the A-tile LDG stream.
// ---------------------------------------------------------------------------
__device__ __forceinline__ void load_tile_async(unsigned dst_u32,
                                                const float* __restrict__ x,
                                                int rowbase, int tid) {
#pragma unroll
    for (int i = 0; i < 16; i++) {
        int idx = tid + i * 256;      // 0..4095
        int row = idx >> 5;           // 0..127
        int q   = idx & 31;           // float4 chunk
        cp16(dst_u32 + (unsigned)(row * RSTRIDE + q * 4) * 4u,
             x + (size_t)(rowbase + row) * DIM + q * 4);
    }
}

// ---------------------------------------------------------------------------
// Main persistent kernel: triangle tile-pairs (ti <= tj).
//  - B operand from smem (double-buffered, cp.async.cg)
//  - A operand DIRECT FROM GLOBAL (warp-broadcast LDG.64, L1-resident, one-k2
//    software prefetch) -> smem crossbar demand halves to 0.5 B/MAC.
//  - packed fma.rn.f32x2 accumulation over k pairs
//  - direct REDG atomics for both mining sides (no staging barriers)
// ---------------------------------------------------------------------------
__global__ void __launch_bounds__(256, 1)
triplet_main_kernel(const float* __restrict__ x, float* __restrict__ out, int out_size) {
    extern __shared__ float smem[];
    float* Bs0   = smem;                       // [128][132]
    float* Bs1   = smem + TILE_F;
    float* sqjs  = smem + 2 * TILE_F;          // [2][128]
    int*   labjs = (int*)(sqjs + 2 * BN);      // [2][128]

    const int tid = threadIdx.x;
    const int tx = tid & 15, ty = tid >> 4;

    const unsigned Bs0_u   = smem_u32(Bs0);
    const unsigned Bs1_u   = smem_u32(Bs1);
    const unsigned sqjs_u  = smem_u32(sqjs);
    const unsigned labjs_u = smem_u32(labjs);

    // Static contiguous unit range (row-major triangle order -> A reuse in L1).
    int u0 = (int)((long long)blockIdx.x * NUNITS / gridDim.x);
    int u1 = (int)((long long)(blockIdx.x + 1) * NUNITS / gridDim.x);

    int ti = 0, rem = u0;
    while (rem >= NTILES - ti) { rem -= NTILES - ti; ti++; }
    int tj = ti + rem;

    // Prologue: B(u0) tile + meta
    load_tile_async(Bs0_u, x, tj * BN, tid);
    if (tid < BN) {
        cp4(sqjs_u + tid * 4,  g_sq  + tj * BN + tid);
        cp4(labjs_u + tid * 4, g_lab + tj * BN + tid);
    }
    cp_commit();

    for (int u = u0; u < u1; ++u) {
        const int buf = (u - u0) & 1;
        int nti = ti, ntj = tj + 1;
        if (ntj == NTILES) { nti = ti + 1; ntj = nti; }
        const bool has_next = (u + 1 < u1);

        if (has_next) {
            load_tile_async(buf ? Bs0_u : Bs1_u, x, ntj * BN, tid);
            if (tid < BN) {
                cp4(sqjs_u + ((buf ^ 1) * BN + tid) * 4,  g_sq  + ntj * BN + tid);
                cp4(labjs_u + ((buf ^ 1) * BN + tid) * 4, g_lab + ntj * BN + tid);
            }
            cp_commit();
            cp_wait1();
        } else {
            cp_wait0();
        }
        __syncthreads();

        const int ibase = ti * BM;
        // A base for this thread's first row (row = ibase + ty + 16r).
        const char* aG = (const char*)x + (size_t)(ibase + ty) * (DIM * 4);
        const char* bB = (const char*)(buf ? Bs1 : Bs0) + tx * (RSTRIDE * 4);

        // ---- GEMM: acc[r][c] holds packed (even-k, odd-k) partial sums ----
        u64 acc[8][8];
#pragma unroll
        for (int r = 0; r < 8; r++)
#pragma unroll
            for (int c = 0; c < 8; c++) acc[r][c] = 0ull;

        u64 aE[8], aO[8];
#pragma unroll
        for (int r = 0; r < 8; r++)
            aE[r] = __ldg((const u64*)(aG + r * (16 * DIM * 4)));

#pragma unroll 8
        for (int k4 = 0; k4 < DIM / 4; ++k4) {
            // ---- half 1: k2 = 2*k4 ----
            u64 b0[8];
#pragma unroll
            for (int c = 0; c < 8; c++)
                b0[c] = *(const u64*)(bB + c * (16 * RSTRIDE * 4) + (2 * k4) * 8);
#pragma unroll
            for (int r = 0; r < 8; r++)     // prefetch odd k2
                aO[r] = __ldg((const u64*)(aG + r * (16 * DIM * 4) + (2 * k4 + 1) * 8));
#pragma unroll
            for (int r = 0; r < 8; r++)
#pragma unroll
                for (int c = 0; c < 8; c++)
                    asm("fma.rn.f32x2 %0, %1, %2, %0;"
                        : "+l"(acc[r][c]) : "l"(aE[r]), "l"(b0[c]));

            // ---- half 2: k2 = 2*k4+1 ----
            u64 b1[8];
#pragma unroll
            for (int c = 0; c < 8; c++)
                b1[c] = *(const u64*)(bB + c * (16 * RSTRIDE * 4) + (2 * k4 + 1) * 8);
            {   // prefetch next even k2 (clamped in-bounds at the tail)
                int kn = (k4 < DIM / 4 - 1) ? (2 * k4 + 2) : (DIM / 2 - 1);
#pragma unroll
                for (int r = 0; r < 8; r++)
                    aE[r] = __ldg((const u64*)(aG + r * (16 * DIM * 4) + kn * 8));
            }
#pragma unroll
            for (int r = 0; r < 8; r++)
#pragma unroll
                for (int c = 0; c < 8; c++)
                    asm("fma.rn.f32x2 %0, %1, %2, %0;"
                        : "+l"(acc[r][c]) : "l"(aO[r]), "l"(b1[c]));
        }

        // ---- Epilogue: d^2 mining, row (i) and column (j) sides ----
        float sjv[8]; int ljv[8];
#pragma unroll
        for (int c = 0; c < 8; c++) {
            sjv[c] = sqjs[buf * BN + tx + 16 * c];
            ljv[c] = labjs[buf * BN + tx + 16 * c];
        }
        float ap[8], an[8], apc[8], anc[8];
#pragma unroll
        for (int i = 0; i < 8; i++) {
            ap[i] = 0.0f;  an[i] = __int_as_float(0x7f800000);
            apc[i] = 0.0f; anc[i] = __int_as_float(0x7f800000);
        }
#pragma unroll
        for (int r = 0; r < 8; r++) {
            int row = ibase + ty + 16 * r;
            float si = __ldg(&g_sq[row]);
            int   li = __ldg(&g_lab[row]);
#pragma unroll
            for (int c = 0; c < 8; c++) {
                float2 p = *reinterpret_cast<float2*>(&acc[r][c]);
                float d2 = fmaf(-2.0f, p.x + p.y, si + sjv[c]);
                d2 = fmaxf(d2, 1e-12f);
                if (li == ljv[c]) { ap[r] = fmaxf(ap[r], d2); apc[c] = fmaxf(apc[c], d2); }
                else              { an[r] = fminf(an[r], d2); anc[c] = fminf(anc[c], d2); }
            }
        }

        // Row side: reduce over 16 tx-lanes (xor 8,4,2,1 stays in each half),
        // then direct atomics (d2 > 0 -> uint order == float order).
#pragma unroll
        for (int o = 8; o; o >>= 1)
#pragma unroll
            for (int r = 0; r < 8; r++) {
                ap[r] = fmaxf(ap[r], __shfl_xor_sync(0xffffffffu, ap[r], o));
                an[r] = fminf(an[r], __shfl_xor_sync(0xffffffffu, an[r], o));
            }
        if (tx == 0) {
#pragma unroll
            for (int r = 0; r < 8; r++) {
                int row = ibase + ty + 16 * r;
                atomicMax(&g_ap2[row], __float_as_uint(ap[r]));
                atomicMin(&g_an2[row], __float_as_uint(an[r]));
            }
        }

        // Col side: fold the ty-pair (lane ^ 16), then direct atomics from the
        // low half-warp — 16 lanes x 8 c cover all 128 columns of the tile.
#pragma unroll
        for (int c = 0; c < 8; c++) {
            apc[c] = fmaxf(apc[c], __shfl_xor_sync(0xffffffffu, apc[c], 16));
            anc[c] = fminf(anc[c], __shfl_xor_sync(0xffffffffu, anc[c], 16));
        }
        if ((tid & 16) == 0) {
#pragma unroll
            for (int c = 0; c < 8; c++) {
                int col = tj * BN + tx + 16 * c;
                atomicMax(&g_ap2[col], __float_as_uint(apc[c]));
                atomicMin(&g_an2[col], __float_as_uint(anc[c]));
            }
        }
        __syncthreads();   // all reads of current B buffer done before next cp.async

        ti = nti; tj = ntj;
    }

    // ---- Inline finalize: last CTA computes loss + precision ----
    __threadfence();
    __syncthreads();
    __shared__ unsigned s_rank;
    if (tid == 0) s_rank = atomicAdd(&g_done, 1u);
    __syncthreads();
    if (s_rank == (unsigned)(gridDim.x - 1)) {
        float* scrL = Bs0;         // reuse B smem as reduction scratch
        float* scrP = Bs0 + 256;
        float loss = 0.0f, prec = 0.0f;
        for (int i = tid; i < NROWS; i += 256) {
            float dap = sqrtf(__uint_as_float(__ldcg(&g_ap2[i])));
            float dan = sqrtf(__uint_as_float(__ldcg(&g_an2[i])));
            loss += fmaxf(0.0f, MARGIN_F - (dan - dap));
            prec += (dan > dap) ? 1.0f : 0.0f;
        }
        scrL[tid] = loss;
        scrP[tid] = prec;
        __syncthreads();
#pragma unroll
        for (int s = 128; s > 0; s >>= 1) {
            if (tid < s) {
                scrL[tid] += scrL[tid + s];
                scrP[tid] += scrP[tid + s];
            }
            __syncthreads();
        }
        if (tid == 0) {
            out[0] = scrL[0] / (float)NROWS;
            if (out_size > 1) out[1] = scrP[0] / (float)NROWS;
            g_done = 0;  // reset for next graph replay
        }
    }
}

// ---------------------------------------------------------------------------
extern "C" void kernel_launch(void* const* d_in, const int* in_sizes, int n_in,
                              void* d_out, int out_size) {
    const float* x   = (const float*)d_in[0];
    const int*   t32 = (const int*)d_in[1];
    (void)in_sizes; (void)n_in;

    const int smem_bytes = (2 * TILE_F + 2 * BN + 2 * BN) * 4;
    cudaFuncSetAttribute(triplet_main_kernel,
                         cudaFuncAttributeMaxDynamicSharedMemorySize, smem_bytes);

    prep_kernel<<<NROWS * 32 / 256, 256>>>(x, t32);
    triplet_main_kernel<<<GRID_MAIN, 256, smem_bytes>>>(x, (float*)d_out, out_size);
}

// round 9
// speedup vs baseline: 1.0080x; 1.0080x over previous
#include <cuda_runtime.h>
#include <cstdint>

#define NROWS 8192
#define DIM   128
#define BM    128
#define BN    128
#define NTILES (NROWS / BN)                  // 64
#define NUNITS (NTILES * (NTILES + 1) / 2)   // 2080 triangle tile-pairs
#define GRID_MAIN 148
#define NTHREADS 512
#define RSTRIDE   130                        // floats/row: u64-stride 65 (odd) -> LDS.64 conflict-free
#define TILE_F (BM * RSTRIDE)                // 16640 floats per tile
#define MARGIN_F 0.3f

typedef unsigned long long u64;

// Scratch (device globals; no allocations allowed)
__device__ unsigned int g_ap2[NROWS];   // max same-label d^2 (float bits)
__device__ unsigned int g_an2[NROWS];   // min diff-label d^2 (float bits)
__device__ float        g_sq[NROWS];    // ||x_i||^2
__device__ int          g_lab[NROWS];   // normalized labels (int32)
__device__ unsigned int g_done;         // last-CTA election (reset each launch)

// ---------------------------------------------------------------------------
// Helpers
// ---------------------------------------------------------------------------
__device__ __forceinline__ unsigned smem_u32(const void* p) {
    unsigned r;
    asm("{ .reg .u64 t; cvta.to.shared.u64 t, %1; cvt.u32.u64 %0, t; }"
        : "=r"(r) : "l"(p));
    return r;
}
__device__ __forceinline__ void cp8(unsigned dst, const void* src) {
    asm volatile("cp.async.ca.shared.global [%0], [%1], 8;" :: "r"(dst), "l"(src));
}
__device__ __forceinline__ void cp4(unsigned dst, const void* src) {
    asm volatile("cp.async.ca.shared.global [%0], [%1], 4;" :: "r"(dst), "l"(src));
}
__device__ __forceinline__ void cp_commit() { asm volatile("cp.async.commit_group;"); }
__device__ __forceinline__ void cp_wait0()  { asm volatile("cp.async.wait_group 0;" ::: "memory"); }
__device__ __forceinline__ void cp_wait1()  { asm volatile("cp.async.wait_group 1;" ::: "memory"); }
__device__ __forceinline__ void cp_wait2()  { asm volatile("cp.async.wait_group 2;" ::: "memory"); }

// ---------------------------------------------------------------------------
// Fused prep: init mining buffers + row norms + label normalization.
// ---------------------------------------------------------------------------
__global__ void prep_kernel(const float* __restrict__ x, const int* __restrict__ t32) {
    int gid = blockIdx.x * 256 + threadIdx.x;
    if (gid < NROWS) { g_ap2[gid] = 0u; g_an2[gid] = 0x7f800000u; }

    int gwarp = gid >> 5;          // exactly 8192 warps
    int lane  = gid & 31;
    float4 v = reinterpret_cast<const float4*>(x + (size_t)gwarp * DIM)[lane];
    float s = v.x * v.x + v.y * v.y + v.z * v.z + v.w * v.w;
#pragma unroll
    for (int o = 16; o; o >>= 1) s += __shfl_xor_sync(0xffffffffu, s, o);
    if (lane == 0) g_sq[gwarp] = s;

    if (blockIdx.x == 0) {
        // targets may be int64 (odd int32 words all zero) or int32
        __shared__ int s_all64;
        if (threadIdx.x == 0) s_all64 = 1;
        __syncthreads();
        int local = 1;
        for (int i = threadIdx.x; i < 4096; i += 256)
            if (t32[2 * i + 1] != 0) local = 0;
        if (!local) atomicAnd(&s_all64, 0);
        __syncthreads();
        const bool is64 = (s_all64 != 0);
        for (int i = threadIdx.x; i < NROWS; i += 256)
            g_lab[i] = is64 ? t32[2 * i] : t32[i];
    }
}

// ---------------------------------------------------------------------------
// Tile loader: global row-major [rows][128] -> smem rows of stride 130 floats
// (8B-aligned rows: 520 mod 8 == 0). 512 threads, 8 iterations.
// ---------------------------------------------------------------------------
__device__ __forceinline__ void load_tile_async(unsigned dst_u32,
                                                const float* __restrict__ x,
                                                int rowbase, int tid) {
#pragma unroll
    for (int i = 0; i < 8; i++) {
        int idx = tid + i * NTHREADS;  // 0..4095
        int row = idx >> 5;            // 0..127
        int q   = idx & 31;            // float4 chunk
        const float* src = x + (size_t)(rowbase + row) * DIM + q * 4;
        unsigned d = dst_u32 + (unsigned)(row * RSTRIDE + q * 4) * 4u;
        cp8(d, src);
        cp8(d + 8, src + 2);
    }
}

// ---------------------------------------------------------------------------
// Main persistent kernel: triangle tile-pairs (ti <= tj).
// 512 threads (4 warps/SMSP for latency hiding), 8x4 micro-tile, packed
// fma.rn.f32x2, double-buffered B, aliased-diagonal async A refill,
// inline finalize.
// Thread grid: tx = lane (0..31) -> cols tx+32c (c<4); ty = warp (0..15)
// -> rows ty+16r (r<8). A-loads warp-broadcast; B-loads conflict-free
// (u64 row stride 65, (lane*65) mod 16 bijective per phase).
// ---------------------------------------------------------------------------
__global__ void __launch_bounds__(NTHREADS, 1)
triplet_main_kernel(const float* __restrict__ x, float* __restrict__ out, int out_size) {
    extern __shared__ float smem[];
    float* Bs0   = smem;                       // [128][130]
    float* Bs1   = smem + TILE_F;
    float* As    = smem + 2 * TILE_F;          // [128][130]
    float* sqis  = smem + 3 * TILE_F;          // [128]
    int*   labis = (int*)(sqis + BM);          // [128]
    float* sqjs  = (float*)(labis + BM);       // [2][128]
    int*   labjs = (int*)(sqjs + 2 * BN);      // [2][128]
    float* colAp = (float*)(labjs + 2 * BN);   // [16][128]
    float* colAn = colAp + 16 * BN;            // [16][128]

    const int tid = threadIdx.x;
    const int tx = tid & 31;        // lane -> column group
    const int ty = tid >> 5;        // warp -> row group (0..15)

    const unsigned Bs0_u   = smem_u32(Bs0);
    const unsigned Bs1_u   = smem_u32(Bs1);
    const unsigned As_u    = smem_u32(As);
    const unsigned sqis_u  = smem_u32(sqis);
    const unsigned labis_u = smem_u32(labis);
    const unsigned sqjs_u  = smem_u32(sqjs);
    const unsigned labjs_u = smem_u32(labjs);

    // Static contiguous unit range (row-major triangle order -> A-tile reuse).
    int u0 = (int)((long long)blockIdx.x * NUNITS / gridDim.x);
    int u1 = (int)((long long)(blockIdx.x + 1) * NUNITS / gridDim.x);

    int ti = 0, rem = u0;
    while (rem >= NTILES - ti) { rem -= NTILES - ti; ti++; }
    int tj = ti + rem;

    // Prologue group: A tile + B(u0) tile + meta
    load_tile_async(As_u, x, ti * BM, tid);
    load_tile_async(Bs0_u, x, tj * BN, tid);
    if (tid < BM) {
        cp4(sqis_u + tid * 4,  g_sq  + ti * BM + tid);
        cp4(labis_u + tid * 4, g_lab + ti * BM + tid);
        cp4(sqjs_u + tid * 4,  g_sq  + tj * BN + tid);
        cp4(labjs_u + tid * 4, g_lab + tj * BN + tid);
    }
    cp_commit();

    bool alias = false;  // current unit reads A from its B buffer (fresh diagonal)

    for (int u = u0; u < u1; ++u) {
        const int buf = (u - u0) & 1;
        int nti = ti, ntj = tj + 1;
        if (ntj == NTILES) { nti = ti + 1; ntj = nti; }
        const bool has_next = (u + 1 < u1);

        int ncommit = 0;
        if (has_next) {
            load_tile_async(buf ? Bs0_u : Bs1_u, x, ntj * BN, tid);
            if (tid < BN) {
                cp4(sqjs_u + ((buf ^ 1) * BN + tid) * 4,  g_sq  + ntj * BN + tid);
                cp4(labjs_u + ((buf ^ 1) * BN + tid) * 4, g_lab + ntj * BN + tid);
            }
            cp_commit(); ncommit++;
        }
        // Aliased diagonal: As is idle this unit -> refill it asynchronously,
        // but only if a same-row (non-diagonal) unit will actually use it.
        if (alias && has_next && nti == ti) {
            load_tile_async(As_u, x, ti * BM, tid);
            if (tid < BM) {
                cp4(sqis_u + tid * 4,  g_sq  + ti * BM + tid);
                cp4(labis_u + tid * 4, g_lab + ti * BM + tid);
            }
            cp_commit(); ncommit++;
        }
        if (ncommit == 0)      cp_wait0();
        else if (ncommit == 1) cp_wait1();
        else                   cp_wait2();
        __syncthreads();

        const float* bbuf  = buf ? Bs1 : Bs0;
        const float* abuf  = alias ? bbuf : As;
        const float* sqip  = alias ? (sqjs + buf * BN)  : sqis;
        const int*   labip = alias ? (labjs + buf * BN) : labis;

        // ---- GEMM: acc[r][c] holds packed (even-k, odd-k) partial sums ----
        u64 acc[8][4];
#pragma unroll
        for (int r = 0; r < 8; r++)
#pragma unroll
            for (int c = 0; c < 4; c++) acc[r][c] = 0ull;

        const char* aB = (const char*)abuf + ty * (RSTRIDE * 4);   // rows ty+16r
        const char* bB = (const char*)bbuf + tx * (RSTRIDE * 4);   // cols tx+32c

#pragma unroll 4
        for (int k2 = 0; k2 < DIM / 2; ++k2) {
            u64 a[8], b[4];
#pragma unroll
            for (int r = 0; r < 8; r++)
                a[r] = *(const u64*)(aB + r * (16 * RSTRIDE * 4) + k2 * 8);
#pragma unroll
            for (int c = 0; c < 4; c++)
                b[c] = *(const u64*)(bB + c * (32 * RSTRIDE * 4) + k2 * 8);
#pragma unroll
            for (int r = 0; r < 8; r++)
#pragma unroll
                for (int c = 0; c < 4; c++)
                    asm("fma.rn.f32x2 %0, %1, %2, %0;"
                        : "+l"(acc[r][c]) : "l"(a[r]), "l"(b[c]));
        }

        // ---- Epilogue: d^2 mining, row (i) and column (j) sides ----
        float sjv[4]; int ljv[4];
#pragma unroll
        for (int c = 0; c < 4; c++) {
            sjv[c] = sqjs[buf * BN + tx + 32 * c];
            ljv[c] = labjs[buf * BN + tx + 32 * c];
        }
        float ap[8], an[8], apc[4], anc[4];
#pragma unroll
        for (int r = 0; r < 8; r++) { ap[r] = 0.0f; an[r] = __int_as_float(0x7f800000); }
#pragma unroll
        for (int c = 0; c < 4; c++) { apc[c] = 0.0f; anc[c] = __int_as_float(0x7f800000); }
#pragma unroll
        for (int r = 0; r < 8; r++) {
            float si = sqip[ty + 16 * r];
            int   li = labip[ty + 16 * r];
#pragma unroll
            for (int c = 0; c < 4; c++) {
                float2 p = *reinterpret_cast<float2*>(&acc[r][c]);
                float d2 = fmaf(-2.0f, p.x + p.y, si + sjv[c]);
                d2 = fmaxf(d2, 1e-12f);
                if (li == ljv[c]) { ap[r] = fmaxf(ap[r], d2); apc[c] = fmaxf(apc[c], d2); }
                else              { an[r] = fminf(an[r], d2); anc[c] = fminf(anc[c], d2); }
            }
        }

        // Row side: rows identical across the warp -> full 32-lane reduce,
        // lane 0 atomics (d2 > 0 -> uint order == float order).
#pragma unroll
        for (int o = 16; o; o >>= 1)
#pragma unroll
            for (int r = 0; r < 8; r++) {
                ap[r] = fmaxf(ap[r], __shfl_xor_sync(0xffffffffu, ap[r], o));
                an[r] = fminf(an[r], __shfl_xor_sync(0xffffffffu, an[r], o));
            }
        if (tx == 0) {
#pragma unroll
            for (int r = 0; r < 8; r++) {
                int row = ti * BM + ty + 16 * r;
                atomicMax(&g_ap2[row], __float_as_uint(ap[r]));
                atomicMin(&g_an2[row], __float_as_uint(an[r]));
            }
        }

        // Col side: stage per-warp partials (each warp covers all 128 cols),
        // combine across the 16 warps, then atomics.
#pragma unroll
        for (int c = 0; c < 4; c++) {
            colAp[ty * BN + tx + 32 * c] = apc[c];
            colAn[ty * BN + tx + 32 * c] = anc[c];
        }
        __syncthreads();
        if (tid < BN) {
            float ca = colAp[tid], cn = colAn[tid];
#pragma unroll
            for (int w = 1; w < 16; w++) {
                ca = fmaxf(ca, colAp[w * BN + tid]);
                cn = fminf(cn, colAn[w * BN + tid]);
            }
            atomicMax(&g_ap2[tj * BN + tid], __float_as_uint(ca));
            atomicMin(&g_an2[tj * BN + tid], __float_as_uint(cn));
        }
        __syncthreads();

        alias = has_next && (nti != ti);  // next unit is a fresh diagonal
        ti = nti; tj = ntj;
    }

    // ---- Inline finalize: last CTA computes loss + precision ----
    __threadfence();
    __syncthreads();
    __shared__ unsigned s_rank;
    if (tid == 0) s_rank = atomicAdd(&g_done, 1u);
    __syncthreads();
    if (s_rank == (unsigned)(gridDim.x - 1)) {
        float* scrL = Bs0;          // reuse B smem as reduction scratch
        float* scrP = Bs0 + NTHREADS;
        float loss = 0.0f, prec = 0.0f;
        for (int i = tid; i < NROWS; i += NTHREADS) {
            float dap = sqrtf(__uint_as_float(__ldcg(&g_ap2[i])));
            float dan = sqrtf(__uint_as_float(__ldcg(&g_an2[i])));
            loss += fmaxf(0.0f, MARGIN_F - (dan - dap));
            prec += (dan > dap) ? 1.0f : 0.0f;
        }
        scrL[tid] = loss;
        scrP[tid] = prec;
        __syncthreads();
#pragma unroll
        for (int s = NTHREADS / 2; s > 0; s >>= 1) {
            if (tid < s) {
                scrL[tid] += scrL[tid + s];
                scrP[tid] += scrP[tid + s];
            }
            __syncthreads();
        }
        if (tid == 0) {
            out[0] = scrL[0] / (float)NROWS;
            if (out_size > 1) out[1] = scrP[0] / (float)NROWS;
            g_done = 0;  // reset for next graph replay
        }
    }
}

// ---------------------------------------------------------------------------
extern "C" void kernel_launch(void* const* d_in, const int* in_sizes, int n_in,
                              void* d_out, int out_size) {
    const float* x   = (const float*)d_in[0];
    const int*   t32 = (const int*)d_in[1];
    (void)in_sizes; (void)n_in;

    const int smem_bytes =
        (3 * TILE_F + BM + BM + 2 * BN + 2 * BN + 16 * BN + 16 * BN) * 4;
    cudaFuncSetAttribute(triplet_main_kernel,
                         cudaFuncAttributeMaxDynamicSharedMemorySize, smem_bytes);

    prep_kernel<<<NROWS * 32 / 256, 256>>>(x, t32);
    triplet_main_kernel<<<GRID_MAIN, NTHREADS, smem_bytes>>>(x, (float*)d_out, out_size);
}